// round 3
// baseline (speedup 1.0000x reference)
#include <cuda_runtime.h>
#include <cuda_bf16.h>
#include <cstddef>

// Problem constants: B=32, H=W=64, C=64, K=3, S=1, PAD=1
// Hp=Wp=66, out1=out2=64, OUT = out*K = 192
#define HP      66
#define NP      (HP * HP)        // 4356 floats per (b,c2) t-window
#define CH      64
#define HW      64
#define OUT     192
#define BATCH   32

// out[b, c2, r, s]  (raw-reshaped to (B,192,192,C) == same linear buffer)
//   t  = c2*4356 + ip*66 + jp,  ip = r/3 + r%3,  jp = s/3 + s%3
//   p  = t >> 6,  c = t & 63,  rp = p/66, cp = p%66
//   value = (1<=rp<=64 && 1<=cp<=64) ? in[b, rp-1, cp-1, c] : 0
// pixel index (rp-1)*64 + (cp-1) simplifies to p - 2*rp - 65.

__global__ __launch_bounds__(192)
void padding_jacobians_kernel(const float* __restrict__ in,
                              float* __restrict__ out) {
    __shared__ float sm[NP];               // 17424 B

    const unsigned c2 = blockIdx.x;        // 0..63
    const unsigned b  = blockIdx.y;        // 0..31
    const int tx  = threadIdx.x;           // 0..47  (s-quad index)
    const int ty  = threadIdx.y;           // 0..3
    const int tid = ty * 48 + tx;

    const float* __restrict__ inb = in + (size_t)b * (HW * HW * CH);
    const unsigned base_t = c2 * NP;       // multiple of 4

    // ---- Load phase: sm[i] = up_flat[base_t + i], zero on padded border ----
    // 4356/4 = 1089 float4s. A float4 never crosses a p boundary
    // (t multiple of 4, c = t&63, 4 | 64).
    #pragma unroll 1
    for (unsigned q = tid; q < NP / 4; q += 192) {
        unsigned t  = base_t + 4u * q;
        unsigned p  = t >> 6;
        unsigned c  = t & 63u;
        unsigned rp = (p * 993u) >> 16;    // == p/66 for p < 4356 (verified exact)
        unsigned cp = p - 66u * rp;
        float4 v = make_float4(0.f, 0.f, 0.f, 0.f);
        if ((rp - 1u) < 64u && (cp - 1u) < 64u) {
            // interior: pixel = p - 2*rp - 65, contiguous 64-float channel row
            v = *reinterpret_cast<const float4*>(inb + ((p - 2u * rp - 65u) << 6) + c);
        }
        reinterpret_cast<float4*>(sm)[q] = v;
    }
    __syncthreads();

    // ---- Store phase: expand sm window to 192x192 tile, float4 stores ----
    const int s0 = 4 * tx;
    const int jp0 =  s0      / 3 +  s0      % 3;
    const int jp1 = (s0 + 1) / 3 + (s0 + 1) % 3;
    const int jp2 = (s0 + 2) / 3 + (s0 + 2) % 3;
    const int jp3 = (s0 + 3) / 3 + (s0 + 3) % 3;

    float* __restrict__ outp =
        out + (size_t)(b * 64 + c2) * (OUT * OUT) + s0;

    // maintain o = r/3, k = r%3 incrementally as r steps by 4
    int o = ty / 3;      // ty in 0..3
    int k = ty % 3;
    #pragma unroll 4
    for (int r = ty; r < OUT; r += 4) {
        const float* row = sm + (o + k) * HP;   // ip = o + k, ip*66
        float4 v = make_float4(row[jp0], row[jp1], row[jp2], row[jp3]);
        *reinterpret_cast<float4*>(outp + (size_t)r * OUT) = v;
        o += (k < 2) ? 1 : 2;                   // (r+4)/3
        k = (k == 2) ? 0 : (k + 1);             // (r+4)%3
    }
}

extern "C" void kernel_launch(void* const* d_in, const int* in_sizes, int n_in,
                              void* d_out, int out_size) {
    const float* in  = (const float*)d_in[0];
    float*       out = (float*)d_out;
    (void)in_sizes; (void)n_in; (void)out_size;

    dim3 grid(64, BATCH);     // (c2, b)
    dim3 block(48, 4);        // 192 threads
    padding_jacobians_kernel<<<grid, block>>>(in, out);
}